// round 4
// baseline (speedup 1.0000x reference)
#include <cuda_runtime.h>
#include <cstdint>
#include <math.h>

#define BB    512
#define STATE 256
#define DES   128
#define H     512
#define SPLITS 18
#define SAW   136   // sA row stride in words: 136 mod 32 = 8 -> conflict-free

__device__ float g_buf0[BB * H];
__device__ float g_buf1[BB * H];
__device__ float g_part[SPLITS][BB][H];

__device__ __forceinline__ uint32_t pack_h2(float lo, float hi) {
    uint32_t r;
    asm("cvt.rn.f16x2.f32 %0, %1, %2;" : "=r"(r) : "f"(hi), "f"(lo));
    return r;
}
__device__ __forceinline__ void mma16816(float* c,
                                         uint32_t a0, uint32_t a1, uint32_t a2, uint32_t a3,
                                         uint32_t b0, uint32_t b1) {
    asm volatile("mma.sync.aligned.m16n8k16.row.col.f32.f16.f16.f32 "
                 "{%0,%1,%2,%3}, {%4,%5,%6,%7}, {%8,%9}, {%0,%1,%2,%3};"
                 : "+f"(c[0]), "+f"(c[1]), "+f"(c[2]), "+f"(c[3])
                 : "r"(a0), "r"(a1), "r"(a2), "r"(a3), "r"(b0), "r"(b1));
}

// ---------------------------------------------------------------------------
// Embed: out = tanh(state @ embed_w + embed_b)
// ---------------------------------------------------------------------------
__global__ void embed_kernel(const float* __restrict__ state,
                             const float* __restrict__ ew,
                             const float* __restrict__ eb) {
    int idx = blockIdx.x * blockDim.x + threadIdx.x;
    int b = idx >> 9;
    int j = idx & 511;
    float s = eb[j];
    const float* sp = state + b * STATE;
#pragma unroll 8
    for (int k = 0; k < STATE; k++)
        s = fmaf(sp[k], ew[k * H + j], s);
    g_buf0[idx] = tanhf(s);
}

// ---------------------------------------------------------------------------
// fp16 m16n8k16 split-K GEMM, pipelined.
//   virtual A[b, d*512+h] = cmd[b,d] * in[b,h]   (chunk d=128 -> hw_b, scale 1)
// CTA 128x128, 8 warps (2x4 of 64x32 warp tiles). A via smem (fp16 pair-major,
// double buffered); B fragments loaded straight from gmem (sector-perfect).
// ---------------------------------------------------------------------------
__global__ void __launch_bounds__(256, 1)
gemm_fp16(int layer, const float* __restrict__ cmd,
          const float* __restrict__ hwW, const float* __restrict__ hwb)
{
    __shared__ __align__(16) uint32_t sA[2][8 * SAW];   // [kpair][m] f16x2

    const int t    = threadIdx.x;
    const int lane = t & 31;
    const int w    = t >> 5;
    const int wm   = w & 1;          // 64-row group
    const int wn   = w >> 1;         // 32-col group
    const int q    = lane & 3;
    const int r4   = lane >> 2;

    const int n0 = blockIdx.x * 128;
    const int m0 = blockIdx.y * 128;
    const int sp = blockIdx.z;
    const int c0  = sp * 7 + (sp < 3 ? sp : 3);
    const int cnt = 7 + (sp < 3 ? 1 : 0);
    const int total = cnt * 32;

    const float* __restrict__ inbuf = layer ? g_buf1 : g_buf0;

    // A staging role: thread covers row am, k-half kh (8 k's = 4 pairs)
    const int am = t & 127;
    const int kh = t >> 7;
    const float* inrow = inbuf + (size_t)(m0 + am) * H + kh * 8;

    float sc[8];
#pragma unroll
    for (int i = 0; i < 8; i++) {
        int d = c0 + i;
        sc[i] = (i < cnt) ? ((d < DES) ? cmd[(m0 + am) * DES + d] : 1.0f) : 0.0f;
    }

    const int bcol = n0 + wn * 32 + r4;   // + ni*8 later

    float acc[4][4][4];
#pragma unroll
    for (int i = 0; i < 4; i++)
#pragma unroll
        for (int j = 0; j < 4; j++)
#pragma unroll
            for (int k = 0; k < 4; k++) acc[i][j][k] = 0.0f;

    // ---- prologue: A regs + B regs for it = 0 ----
    float4 av0 = *(const float4*)(inrow);
    float4 av1 = *(const float4*)(inrow + 4);
    float bcur[4][4], bnxt[4][4];
    {
        const float* bb = ((c0 < DES) ? (hwW + (size_t)c0 * (H * H)) : hwb);
#pragma unroll
        for (int ni = 0; ni < 4; ni++) {
            const float* p = bb + (size_t)(2 * q) * H + bcol + ni * 8;
            bcur[ni][0] = __ldg(p);
            bcur[ni][1] = __ldg(p + H);
            bcur[ni][2] = __ldg(p + 8 * H);
            bcur[ni][3] = __ldg(p + 9 * H);
        }
    }

    for (int it = 0; it < total; it++) {
        const int ci  = it >> 5;
        const int buf = it & 1;

        // ---- stage A tile (scaled, f16x2 pairs) ----
        {
            float s = sc[ci];
            uint32_t h0 = pack_h2(av0.x * s, av0.y * s);
            uint32_t h1 = pack_h2(av0.z * s, av0.w * s);
            uint32_t h2 = pack_h2(av1.x * s, av1.y * s);
            uint32_t h3 = pack_h2(av1.z * s, av1.w * s);
            uint32_t* sa = &sA[buf][kh * 4 * SAW + am];
            sa[0]       = h0;
            sa[SAW]     = h1;
            sa[2 * SAW] = h2;
            sa[3 * SAW] = h3;
        }

        // ---- prefetch it+1 (A regs + B regs) ----
        const int itn = (it + 1 < total) ? it + 1 : it;
        const int cin = itn >> 5;
        const int kbn = (itn & 31) << 4;
        av0 = *(const float4*)(inrow + kbn);
        av1 = *(const float4*)(inrow + kbn + 4);
        {
            int d = c0 + cin;
            const float* bb = ((d < DES) ? (hwW + (size_t)d * (H * H)) : hwb) + (size_t)kbn * H;
#pragma unroll
            for (int ni = 0; ni < 4; ni++) {
                const float* p = bb + (size_t)(2 * q) * H + bcol + ni * 8;
                bnxt[ni][0] = __ldg(p);
                bnxt[ni][1] = __ldg(p + H);
                bnxt[ni][2] = __ldg(p + 8 * H);
                bnxt[ni][3] = __ldg(p + 9 * H);
            }
        }

        __syncthreads();

        // ---- convert current B to f16x2 fragments ----
        uint32_t bf[4][2];
#pragma unroll
        for (int ni = 0; ni < 4; ni++) {
            bf[ni][0] = pack_h2(bcur[ni][0], bcur[ni][1]);
            bf[ni][1] = pack_h2(bcur[ni][2], bcur[ni][3]);
        }

        // ---- A fragments + MMAs ----
        const uint32_t* sa = &sA[buf][0];
#pragma unroll
        for (int mi = 0; mi < 4; mi++) {
            int row = wm * 64 + mi * 16 + r4;
            uint32_t a0 = sa[q * SAW + row];
            uint32_t a1 = sa[q * SAW + row + 8];
            uint32_t a2 = sa[(q + 4) * SAW + row];
            uint32_t a3 = sa[(q + 4) * SAW + row + 8];
#pragma unroll
            for (int ni = 0; ni < 4; ni++)
                mma16816(acc[mi][ni], a0, a1, a2, a3, bf[ni][0], bf[ni][1]);
        }

#pragma unroll
        for (int ni = 0; ni < 4; ni++)
#pragma unroll
            for (int j = 0; j < 4; j++) bcur[ni][j] = bnxt[ni][j];
    }

    // ---- epilogue: write split-K partials ----
#pragma unroll
    for (int mi = 0; mi < 4; mi++) {
#pragma unroll
        for (int ni = 0; ni < 4; ni++) {
            int row = m0 + wm * 64 + mi * 16 + r4;
            int col = n0 + wn * 32 + ni * 8 + q * 2;
            *(float2*)&g_part[sp][row][col]     = make_float2(acc[mi][ni][0], acc[mi][ni][1]);
            *(float2*)&g_part[sp][row + 8][col] = make_float2(acc[mi][ni][2], acc[mi][ni][3]);
        }
    }
}

// ---------------------------------------------------------------------------
// Reduce split-K partials + (c @ hb_W + hb_b) + ReLU.
// ---------------------------------------------------------------------------
__global__ void reduce_bias_relu(const float* __restrict__ cmd,
                                 const float* __restrict__ hbW,
                                 const float* __restrict__ hbb,
                                 float* dst, int dst_is_buf1) {
    int idx = blockIdx.x * blockDim.x + threadIdx.x;
    int b = idx >> 9;
    int o = idx & 511;
    float s = hbb[o];
#pragma unroll
    for (int sp = 0; sp < SPLITS; sp++) s += g_part[sp][b][o];
    const float* cp = cmd + b * DES;
#pragma unroll 16
    for (int k = 0; k < DES; k++)
        s = fmaf(cp[k], hbW[k * H + o], s);
    float r = fmaxf(s, 0.0f);
    if (dst_is_buf1) g_buf1[idx] = r;
    else             dst[idx] = r;
}

// ---------------------------------------------------------------------------
extern "C" void kernel_launch(void* const* d_in, const int* in_sizes, int n_in,
                              void* d_out, int out_size) {
    const float* state = (const float*)d_in[0];
    const float* cmd   = (const float*)d_in[1];
    const float* ew    = (const float*)d_in[2];
    const float* eb    = (const float*)d_in[3];
    const float* hwW   = (const float*)d_in[4];
    const float* hwb   = (const float*)d_in[5];
    const float* hbW   = (const float*)d_in[6];
    const float* hbb   = (const float*)d_in[7];
    float* out = (float*)d_out;

    const size_t HWW_L = (size_t)DES * H * H;
    const size_t HWB_L = (size_t)H * H;
    const size_t HBW_L = (size_t)DES * H;
    const size_t HBB_L = (size_t)H;

    embed_kernel<<<1024, 256>>>(state, ew, eb);

    dim3 grid(4, 4, SPLITS);

    gemm_fp16<<<grid, 256>>>(0, cmd, hwW, hwb);
    reduce_bias_relu<<<1024, 256>>>(cmd, hbW, hbb, out, 1);

    gemm_fp16<<<grid, 256>>>(1, cmd, hwW + HWW_L, hwb + HWB_L);
    reduce_bias_relu<<<1024, 256>>>(cmd, hbW + HBW_L, hbb + HBB_L, out, 0);
}

// round 5
// speedup vs baseline: 1.3766x; 1.3766x over previous
#include <cuda_runtime.h>
#include <cstdint>
#include <math.h>

#define BB    512
#define STATE 256
#define DES   128
#define H     512
#define SPLITS 18
#define SAW   136   // sA row stride (words): conflict-free STS + frag LDS
#define SBW   140   // sB row stride (words): 16B-aligned rows, conflict-free frag LDS

__device__ float g_buf0[BB * H];
__device__ float g_buf1[BB * H];
__device__ float g_part[SPLITS][BB][H];

__device__ __forceinline__ uint32_t pack_h2(float lo, float hi) {
    uint32_t r;
    asm("cvt.rn.f16x2.f32 %0, %1, %2;" : "=r"(r) : "f"(hi), "f"(lo));
    return r;
}
__device__ __forceinline__ void mma16816(float* c,
                                         uint32_t a0, uint32_t a1, uint32_t a2, uint32_t a3,
                                         uint32_t b0, uint32_t b1) {
    asm volatile("mma.sync.aligned.m16n8k16.row.col.f32.f16.f16.f32 "
                 "{%0,%1,%2,%3}, {%4,%5,%6,%7}, {%8,%9}, {%0,%1,%2,%3};"
                 : "+f"(c[0]), "+f"(c[1]), "+f"(c[2]), "+f"(c[3])
                 : "r"(a0), "r"(a1), "r"(a2), "r"(a3), "r"(b0), "r"(b1));
}
__device__ __forceinline__ uint32_t smem_u32(const void* p) {
    uint32_t a;
    asm("{ .reg .u64 t; cvta.to.shared.u64 t, %1; cvt.u32.u64 %0, t; }" : "=r"(a) : "l"(p));
    return a;
}
__device__ __forceinline__ void cp16(uint32_t dst, const float* src) {
    asm volatile("cp.async.ca.shared.global [%0], [%1], 16;" :: "r"(dst), "l"(src));
}
#define CP_COMMIT() asm volatile("cp.async.commit_group;" ::: "memory")
#define CP_WAIT2()  asm volatile("cp.async.wait_group 2;" ::: "memory")

// ---------------------------------------------------------------------------
__global__ void embed_kernel(const float* __restrict__ state,
                             const float* __restrict__ ew,
                             const float* __restrict__ eb) {
    int idx = blockIdx.x * blockDim.x + threadIdx.x;
    int b = idx >> 9;
    int j = idx & 511;
    float s = eb[j];
    const float* sp = state + b * STATE;
#pragma unroll 8
    for (int k = 0; k < STATE; k++)
        s = fmaf(sp[k], ew[k * H + j], s);
    g_buf0[idx] = tanhf(s);
}

// ---------------------------------------------------------------------------
// fp16 m16n8k16 split-K GEMM, cp.async pipelined (4-stage B ring).
//   virtual A[b, d*512+h] = cmd[b,d] * in[b,h]   (chunk d=128 -> hw_b, scale 1)
// CTA 128x128, 8 warps (2x4 of 64x32 warp tiles), 2 CTAs/SM.
// ---------------------------------------------------------------------------
__global__ void __launch_bounds__(256, 2)
gemm_fp16(int layer, const float* __restrict__ cmd,
          const float* __restrict__ hwW, const float* __restrict__ hwb)
{
    __shared__ __align__(16) uint32_t sA[2][8 * SAW];     // f16x2 pair-major
    __shared__ __align__(16) float    sB[4][16 * SBW];    // f32 4-stage ring

    const int t    = threadIdx.x;
    const int lane = t & 31;
    const int w    = t >> 5;
    const int wm   = w & 1;
    const int wn   = w >> 1;
    const int q    = lane & 3;
    const int r4   = lane >> 2;

    const int n0 = blockIdx.x * 128;
    const int m0 = blockIdx.y * 128;
    const int sp = blockIdx.z;
    const int c0  = sp * 7 + (sp < 3 ? sp : 3);
    const int cnt = 7 + (sp < 3 ? 1 : 0);
    const int total = cnt * 32;

    const float* __restrict__ inbuf = layer ? g_buf1 : g_buf0;

    // ---- roles ----
    const int am = t & 127;          // A staging row
    const int kh = t >> 7;           // A staging k-half
    const float* inrow = inbuf + (size_t)(m0 + am) * H + kh * 8;

    // B cp.async role: rows t>>5 and (t>>5)+8, cols (t&31)*4
    const int brow = t >> 5;
    const int bcol4 = (t & 31) * 4;
    const uint32_t sB_base = smem_u32(&sB[0][0]);
    const uint32_t bdst1 = sB_base + (uint32_t)(brow * SBW + bcol4) * 4;
    const uint32_t bdst2 = bdst1 + 8 * SBW * 4;

    float sc[8];
#pragma unroll
    for (int i = 0; i < 8; i++) {
        int d = c0 + i;
        sc[i] = (i < cnt) ? ((d < DES) ? cmd[(m0 + am) * DES + d] : 1.0f) : 0.0f;
    }

    float acc[4][4][4];
#pragma unroll
    for (int i = 0; i < 4; i++)
#pragma unroll
        for (int j = 0; j < 4; j++)
#pragma unroll
            for (int k = 0; k < 4; k++) acc[i][j][k] = 0.0f;

    // helper: issue one B stage's cp.asyncs for iteration j
    auto issueB = [&](int j) {
        int jj = (j < total) ? j : total - 1;
        int d  = c0 + (jj >> 5);
        int kb = (jj & 31) << 4;
        const float* bb = ((d < DES) ? (hwW + (size_t)d * (H * H)) : hwb)
                          + (size_t)kb * H + n0;
        uint32_t slotoff = (uint32_t)(j & 3) * (16 * SBW * 4);
        cp16(bdst1 + slotoff, bb + brow * H + bcol4);
        cp16(bdst2 + slotoff, bb + (brow + 8) * H + bcol4);
        CP_COMMIT();
    };

    // ---- prologue: 3 B stages in flight + A regs for it 0 ----
    issueB(0); issueB(1); issueB(2);
    float4 av0 = *(const float4*)(inrow);
    float4 av1 = *(const float4*)(inrow + 4);

    for (int it = 0; it < total; it++) {
        const int ci  = it >> 5;
        const int buf = it & 1;

        // 1) stage A (scaled, f16x2 pair-major)
        {
            float s = sc[ci];
            uint32_t* sa = &sA[buf][kh * 4 * SAW + am];
            sa[0]       = pack_h2(av0.x * s, av0.y * s);
            sa[SAW]     = pack_h2(av0.z * s, av0.w * s);
            sa[2 * SAW] = pack_h2(av1.x * s, av1.y * s);
            sa[3 * SAW] = pack_h2(av1.z * s, av1.w * s);
        }
        // 2) prefetch A regs for it+1
        {
            int itn = (it + 1 < total) ? it + 1 : it;
            int kbn = (itn & 31) << 4;
            av0 = *(const float4*)(inrow + kbn);
            av1 = *(const float4*)(inrow + kbn + 4);
        }
        // 3) wait for slot it&3, 4) barrier
        CP_WAIT2();
        __syncthreads();
        // 5) refill ring for it+3 (slot was fully consumed at it-1)
        issueB(it + 3);

        // 6) fragments + MMAs
        const float* sb = &sB[it & 3][0];
        const uint32_t* sa = &sA[buf][0];

        uint32_t bf[4][2];
#pragma unroll
        for (int ni = 0; ni < 4; ni++) {
            int col = wn * 32 + ni * 8 + r4;
            float b0 = sb[(2 * q) * SBW + col];
            float b1 = sb[(2 * q + 1) * SBW + col];
            float b2 = sb[(2 * q + 8) * SBW + col];
            float b3 = sb[(2 * q + 9) * SBW + col];
            bf[ni][0] = pack_h2(b0, b1);
            bf[ni][1] = pack_h2(b2, b3);
        }
#pragma unroll
        for (int mi = 0; mi < 4; mi++) {
            int row = wm * 64 + mi * 16 + r4;
            uint32_t a0 = sa[q * SAW + row];
            uint32_t a1 = sa[q * SAW + row + 8];
            uint32_t a2 = sa[(q + 4) * SAW + row];
            uint32_t a3 = sa[(q + 4) * SAW + row + 8];
#pragma unroll
            for (int ni = 0; ni < 4; ni++)
                mma16816(acc[mi][ni], a0, a1, a2, a3, bf[ni][0], bf[ni][1]);
        }
    }

    // ---- epilogue: write split-K partials ----
#pragma unroll
    for (int mi = 0; mi < 4; mi++) {
#pragma unroll
        for (int ni = 0; ni < 4; ni++) {
            int row = m0 + wm * 64 + mi * 16 + r4;
            int col = n0 + wn * 32 + ni * 8 + q * 2;
            *(float2*)&g_part[sp][row][col]     = make_float2(acc[mi][ni][0], acc[mi][ni][1]);
            *(float2*)&g_part[sp][row + 8][col] = make_float2(acc[mi][ni][2], acc[mi][ni][3]);
        }
    }
}

// ---------------------------------------------------------------------------
__global__ void reduce_bias_relu(const float* __restrict__ cmd,
                                 const float* __restrict__ hbW,
                                 const float* __restrict__ hbb,
                                 float* dst, int dst_is_buf1) {
    int idx = blockIdx.x * blockDim.x + threadIdx.x;
    int b = idx >> 9;
    int o = idx & 511;
    float s = hbb[o];
#pragma unroll
    for (int sp = 0; sp < SPLITS; sp++) s += g_part[sp][b][o];
    const float* cp = cmd + b * DES;
#pragma unroll 16
    for (int k = 0; k < DES; k++)
        s = fmaf(cp[k], hbW[k * H + o], s);
    float r = fmaxf(s, 0.0f);
    if (dst_is_buf1) g_buf1[idx] = r;
    else             dst[idx] = r;
}

// ---------------------------------------------------------------------------
extern "C" void kernel_launch(void* const* d_in, const int* in_sizes, int n_in,
                              void* d_out, int out_size) {
    const float* state = (const float*)d_in[0];
    const float* cmd   = (const float*)d_in[1];
    const float* ew    = (const float*)d_in[2];
    const float* eb    = (const float*)d_in[3];
    const float* hwW   = (const float*)d_in[4];
    const float* hwb   = (const float*)d_in[5];
    const float* hbW   = (const float*)d_in[6];
    const float* hbb   = (const float*)d_in[7];
    float* out = (float*)d_out;

    const size_t HWW_L = (size_t)DES * H * H;
    const size_t HWB_L = (size_t)H * H;
    const size_t HBW_L = (size_t)DES * H;
    const size_t HBB_L = (size_t)H;

    embed_kernel<<<1024, 256>>>(state, ew, eb);

    dim3 grid(4, 4, SPLITS);

    gemm_fp16<<<grid, 256>>>(0, cmd, hwW, hwb);
    reduce_bias_relu<<<1024, 256>>>(cmd, hbW, hbb, out, 1);

    gemm_fp16<<<grid, 256>>>(1, cmd, hwW + HWW_L, hwb + HWB_L);
    reduce_bias_relu<<<1024, 256>>>(cmd, hbW + HBW_L, hbb + HBB_L, out, 0);
}

// round 6
// speedup vs baseline: 2.2076x; 1.6037x over previous
#include <cuda_runtime.h>
#include <cstdint>
#include <math.h>

#define BB    512
#define STATE 256
#define DES   128
#define H     512
#define SPLITS 18
#define STG   6
#define SBW   140   // sB row stride (words) -> conflict-free B frag LDS
#define AW    12    // sA row stride (words, 48B) -> conflict-free STS.128 + ldmatrix

#define SA_WORDS (2 * 128 * AW)                       // 3072
#define SMEM_BYTES ((SA_WORDS + STG * 16 * SBW) * 4)  // 66048

__device__ float g_buf0[BB * H];
__device__ float g_buf1[BB * H];
__device__ float g_part[SPLITS][BB][H];

__device__ __forceinline__ uint32_t pack_h2(float lo, float hi) {
    uint32_t r;
    asm("cvt.rn.f16x2.f32 %0, %1, %2;" : "=r"(r) : "f"(hi), "f"(lo));
    return r;
}
__device__ __forceinline__ void mma16816(float* c,
                                         uint32_t a0, uint32_t a1, uint32_t a2, uint32_t a3,
                                         uint32_t b0, uint32_t b1) {
    asm volatile("mma.sync.aligned.m16n8k16.row.col.f32.f16.f16.f32 "
                 "{%0,%1,%2,%3}, {%4,%5,%6,%7}, {%8,%9}, {%0,%1,%2,%3};"
                 : "+f"(c[0]), "+f"(c[1]), "+f"(c[2]), "+f"(c[3])
                 : "r"(a0), "r"(a1), "r"(a2), "r"(a3), "r"(b0), "r"(b1));
}
__device__ __forceinline__ uint32_t smem_u32(const void* p) {
    uint32_t a;
    asm("{ .reg .u64 t; cvta.to.shared.u64 t, %1; cvt.u32.u64 %0, t; }" : "=r"(a) : "l"(p));
    return a;
}
__device__ __forceinline__ void cp16(uint32_t dst, const float* src) {
    asm volatile("cp.async.cg.shared.global [%0], [%1], 16;" :: "r"(dst), "l"(src));
}
__device__ __forceinline__ void ldsm4(uint32_t& a0, uint32_t& a1, uint32_t& a2, uint32_t& a3,
                                      uint32_t addr) {
    asm volatile("ldmatrix.sync.aligned.m8n8.x4.shared.b16 {%0,%1,%2,%3}, [%4];"
                 : "=r"(a0), "=r"(a1), "=r"(a2), "=r"(a3) : "r"(addr));
}
__device__ __forceinline__ void sts128(uint32_t a, uint32_t x, uint32_t y, uint32_t z, uint32_t w) {
    asm volatile("st.shared.v4.b32 [%0], {%1,%2,%3,%4};" :: "r"(a), "r"(x), "r"(y), "r"(z), "r"(w) : "memory");
}
#define CP_COMMIT() asm volatile("cp.async.commit_group;" ::: "memory")
#define CP_WAIT4()  asm volatile("cp.async.wait_group 4;" ::: "memory")

// ---------------------------------------------------------------------------
__global__ void embed_kernel(const float* __restrict__ state,
                             const float* __restrict__ ew,
                             const float* __restrict__ eb) {
    int idx = blockIdx.x * blockDim.x + threadIdx.x;
    int b = idx >> 9;
    int j = idx & 511;
    float s = eb[j];
    const float* sp = state + b * STATE;
#pragma unroll 8
    for (int k = 0; k < STATE; k++)
        s = fmaf(sp[k], ew[k * H + j], s);
    g_buf0[idx] = tanhf(s);
}

// ---------------------------------------------------------------------------
// fp16 m16n8k16 split-K GEMM. 6-stage cp.async B ring, ldmatrix A,
// kb-outer loop (A regs reused across chunks).
//   virtual A[b, d*512+h] = cmd[b,d] * in[b,h]   (chunk d=128 -> hw_b, scale 1)
// ---------------------------------------------------------------------------
__global__ void __launch_bounds__(256, 2)
gemm_fp16(int layer, const float* __restrict__ cmd,
          const float* __restrict__ hwW, const float* __restrict__ hwb)
{
    extern __shared__ __align__(16) uint32_t smw[];
    float* sB = (float*)(smw + SA_WORDS);

    const int t    = threadIdx.x;
    const int lane = t & 31;
    const int w    = t >> 5;
    const int wm   = w & 1;
    const int wn   = w >> 1;
    const int q    = lane & 3;
    const int r4   = lane >> 2;

    const int n0 = blockIdx.x * 128;
    const int m0 = blockIdx.y * 128;
    const int sp = blockIdx.z;
    const int c0  = sp * 7 + (sp < 3 ? sp : 3);
    const int cnt = 7 + (sp < 3 ? 1 : 0);

    const float* __restrict__ inbuf = layer ? g_buf1 : g_buf0;

    // roles
    const int am = t & 127;
    const int kh = t >> 7;
    const float* inrow = inbuf + (size_t)(m0 + am) * H + kh * 8;

    const int brow = t >> 5;
    const int bcol4 = (t & 31) * 4;
    const uint32_t sA_u32 = smem_u32(smw);
    const uint32_t sB_u32 = smem_u32(sB);
    const uint32_t bdst1 = sB_u32 + (uint32_t)(brow * SBW + bcol4) * 4;
    const uint32_t bdst2 = bdst1 + 8 * SBW * 4;

    const uint32_t a_sts = sA_u32 + (uint32_t)(am * AW + kh * 4) * 4;
    const uint32_t a_ldm = sA_u32 + (uint32_t)((wm * 64 + (lane & 15)) * AW) * 4 + (lane >> 4) * 16;

    float sc[8];
#pragma unroll
    for (int i = 0; i < 8; i++) {
        int d = c0 + i;
        sc[i] = (i < cnt) ? ((d < DES) ? cmd[(m0 + am) * DES + d] : 1.0f) : 0.0f;
    }

    float acc[4][4][4];
#pragma unroll
    for (int i = 0; i < 4; i++)
#pragma unroll
        for (int j = 0; j < 4; j++)
#pragma unroll
            for (int k = 0; k < 4; k++) acc[i][j][k] = 0.0f;

    auto issueB = [&](int kbj, int cij, int slot) {
        int d = c0 + cij;
        const float* bb = ((d < DES) ? (hwW + (size_t)d * (H * H)) : hwb)
                          + ((size_t)kbj << 4) * H + n0;
        uint32_t so = (uint32_t)slot * (16 * SBW * 4);
        cp16(bdst1 + so, bb + brow * H + bcol4);
        cp16(bdst2 + so, bb + (brow + 8) * H + bcol4);
        CP_COMMIT();
    };

    // prologue: 5 stages in flight (iters 0..4 are kb=0, ci=0..4 since cnt>=7)
#pragma unroll
    for (int i = 0; i < 5; i++) issueB(0, i, i);
    int kb_is = 0, ci_is = 5;            // coords of iter 5

    float4 av0 = *(const float4*)(inrow);
    float4 av1 = *(const float4*)(inrow + 4);
    float4 nv0 = av0, nv1 = av1;

    int it = 0;
    for (int kb = 0; kb < 32; kb++) {
        for (int ci = 0; ci < cnt; ci++, it++) {
            const int buf = it & 1;
            const uint32_t bufoff = (uint32_t)buf * (128 * AW * 4);

            // stage A (scaled fp16, m-major row) — one STS.128
            {
                float s = sc[ci];
                sts128(a_sts + bufoff,
                       pack_h2(av0.x * s, av0.y * s), pack_h2(av0.z * s, av0.w * s),
                       pack_h2(av1.x * s, av1.y * s), pack_h2(av1.z * s, av1.w * s));
            }
            // prefetch next k-band of A (once per kb)
            if (ci == 0) {
                int kn = (kb < 31) ? kb + 1 : 31;
                nv0 = *(const float4*)(inrow + kn * 16);
                nv1 = *(const float4*)(inrow + kn * 16 + 4);
            }

            CP_WAIT4();
            __syncthreads();

            // keep ring full: issue iter it+5 (coords clamped at the end)
            issueB(kb_is, ci_is, (it + 5) % STG);
            if (++ci_is == cnt) {
                ci_is = 0;
                if (++kb_is == 32) { kb_is = 31; ci_is = cnt - 1; }
            }

            // B fragments (fp32 -> f16x2)
            const float* sb = sB + (it % STG) * (16 * SBW);
            uint32_t bf[4][2];
#pragma unroll
            for (int ni = 0; ni < 4; ni++) {
                int col = wn * 32 + ni * 8 + r4;
                float b0 = sb[(2 * q) * SBW + col];
                float b1 = sb[(2 * q + 1) * SBW + col];
                float b2 = sb[(2 * q + 8) * SBW + col];
                float b3 = sb[(2 * q + 9) * SBW + col];
                bf[ni][0] = pack_h2(b0, b1);
                bf[ni][1] = pack_h2(b2, b3);
            }
            // A fragments via ldmatrix + MMAs
#pragma unroll
            for (int mi = 0; mi < 4; mi++) {
                uint32_t a0, a1, a2, a3;
                ldsm4(a0, a1, a2, a3, a_ldm + bufoff + (uint32_t)(mi * 16 * AW) * 4);
#pragma unroll
                for (int ni = 0; ni < 4; ni++)
                    mma16816(acc[mi][ni], a0, a1, a2, a3, bf[ni][0], bf[ni][1]);
            }
        }
        av0 = nv0; av1 = nv1;
    }

    // epilogue: write split-K partials
#pragma unroll
    for (int mi = 0; mi < 4; mi++) {
#pragma unroll
        for (int ni = 0; ni < 4; ni++) {
            int row = m0 + wm * 64 + mi * 16 + r4;
            int col = n0 + wn * 32 + ni * 8 + q * 2;
            *(float2*)&g_part[sp][row][col]     = make_float2(acc[mi][ni][0], acc[mi][ni][1]);
            *(float2*)&g_part[sp][row + 8][col] = make_float2(acc[mi][ni][2], acc[mi][ni][3]);
        }
    }
}

// ---------------------------------------------------------------------------
__global__ void reduce_bias_relu(const float* __restrict__ cmd,
                                 const float* __restrict__ hbW,
                                 const float* __restrict__ hbb,
                                 float* dst, int dst_is_buf1) {
    int idx = blockIdx.x * blockDim.x + threadIdx.x;
    int b = idx >> 9;
    int o = idx & 511;
    float s = hbb[o];
#pragma unroll
    for (int sp = 0; sp < SPLITS; sp++) s += g_part[sp][b][o];
    const float* cp = cmd + b * DES;
#pragma unroll 16
    for (int k = 0; k < DES; k++)
        s = fmaf(cp[k], hbW[k * H + o], s);
    float r = fmaxf(s, 0.0f);
    if (dst_is_buf1) g_buf1[idx] = r;
    else             dst[idx] = r;
}

// ---------------------------------------------------------------------------
extern "C" void kernel_launch(void* const* d_in, const int* in_sizes, int n_in,
                              void* d_out, int out_size) {
    const float* state = (const float*)d_in[0];
    const float* cmd   = (const float*)d_in[1];
    const float* ew    = (const float*)d_in[2];
    const float* eb    = (const float*)d_in[3];
    const float* hwW   = (const float*)d_in[4];
    const float* hwb   = (const float*)d_in[5];
    const float* hbW   = (const float*)d_in[6];
    const float* hbb   = (const float*)d_in[7];
    float* out = (float*)d_out;

    const size_t HWW_L = (size_t)DES * H * H;
    const size_t HWB_L = (size_t)H * H;
    const size_t HBW_L = (size_t)DES * H;
    const size_t HBB_L = (size_t)H;

    static int smem_set = 0;
    if (!smem_set) {
        cudaFuncSetAttribute(gemm_fp16, cudaFuncAttributeMaxDynamicSharedMemorySize, SMEM_BYTES);
        smem_set = 1;
    }

    embed_kernel<<<1024, 256>>>(state, ew, eb);

    dim3 grid(4, 4, SPLITS);

    gemm_fp16<<<grid, 256, SMEM_BYTES>>>(0, cmd, hwW, hwb);
    reduce_bias_relu<<<1024, 256>>>(cmd, hbW, hbb, out, 1);

    gemm_fp16<<<grid, 256, SMEM_BYTES>>>(1, cmd, hwW + HWW_L, hwb + HWB_L);
    reduce_bias_relu<<<1024, 256>>>(cmd, hbW + HBW_L, hbb + HBB_L, out, 0);
}